// round 10
// baseline (speedup 1.0000x reference)
#include <cuda_runtime.h>
#include <cstdint>

#define NF 27
#define ND 128
#define NB 16384
#define OUT_ROW 479            // 128 + 27*26/2
#define WPC 4                  // warps per CTA; each warp = 2 samples
// half-row buffer: feature f at FOFF(f); 16 chunks x 16B (dims 0..63 or 64..127)
// stride-7 sets {k,k+7,k+14,k+21} get distinct pads {0,16,32,48} -> conflict-free
#define FOFF(f) ((f) * 256 + ((f) / 7) * 16)
#define BUFSZ 6960             // FOFF(26) + 256
#define WARPSM (2 * 2 * BUFSZ) // 2 samples x 2 stage-buffers = 27840
#define CTASM  (WPC * WARPSM)  // 111360 bytes -> 2 CTAs/SM

__device__ __forceinline__ unsigned long long fma2(unsigned long long a,
                                                   unsigned long long b,
                                                   unsigned long long c) {
    unsigned long long d;
    asm("fma.rn.f32x2 %0, %1, %2, %3;" : "=l"(d) : "l"(a), "l"(b), "l"(c));
    return d;
}
__device__ __forceinline__ ulonglong2 lds128(uint32_t addr) {
    ulonglong2 v;
    asm volatile("ld.shared.v2.u64 {%0,%1}, [%2];" : "=l"(v.x), "=l"(v.y) : "r"(addr));
    return v;
}
__device__ __forceinline__ void cp16(uint32_t dst, const float* src) {
    asm volatile("cp.async.ca.shared.global [%0], [%1], 16;"
                 :: "r"(dst), "l"(__cvta_generic_to_global(src)) : "memory");
}
__device__ __forceinline__ void cp_commit() {
    asm volatile("cp.async.commit_group;" ::: "memory");
}
template <int N> __device__ __forceinline__ void cp_wait() {
    asm volatile("cp.async.wait_group %0;" :: "n"(N) : "memory");
}

extern "C" __global__ void __launch_bounds__(WPC * 32, 2)
interaction_kernel(const float* __restrict__ dense,
                   const float* __restrict__ sparse,
                   float* __restrict__ out)
{
    extern __shared__ float smem[];
    uint32_t sb;
    asm("{ .reg .u64 t; cvta.to.shared.u64 t, %1; cvt.u32.u64 %0, t; }"
        : "=r"(sb) : "l"(smem));
    const int warp = threadIdx.x >> 5;
    const int lane = threadIdx.x & 31;
    sb += warp * WARPSM;

    const int b0 = (blockIdx.x * WPC + warp) * 2;   // warp's two samples

    // ---- issue both half-row fills: lane = (fill-sample q, 16B chunk ch)
    const int q  = lane >> 4;
    const int ch = lane & 15;
    #pragma unroll
    for (int st = 0; st < 2; ++st) {
        const uint32_t dbase = sb + q * (2 * BUFSZ) + st * BUFSZ + ch * 16;
        const float* dsrc = dense + (size_t)(b0 + q) * ND + st * 64 + ch * 4;
        cp16(dbase + FOFF(0), dsrc);
        const float* ssrc = sparse + (size_t)(b0 + q) * 26 * ND + st * 64 + ch * 4;
        #pragma unroll
        for (int f = 1; f < NF; ++f)
            cp16(dbase + FOFF(f), ssrc + (size_t)(f - 1) * ND);
        cp_commit();
    }

    // ---- compute setup: half-warp h owns sample b0+h; 16-lane grid 4x4, 7x7 tile
    const int h  = lane >> 4;
    const int rg = (lane >> 2) & 3;
    const int cg = lane & 3;
    const uint32_t mybuf = sb + h * (2 * BUFSZ);

    uint32_t aoff[7], boff[7];
    #pragma unroll
    for (int k = 0; k < 7; ++k) {
        int r = rg * 7 + k; if (r > 26) r = 26;     // clamp; never stored
        aoff[k] = FOFF(r);
    }
    #pragma unroll
    for (int m = 0; m < 7; ++m) {
        int j = cg * 7 + m; if (j > 26) j = 26;
        boff[m] = FOFF(j);
    }

    unsigned long long acc[7][7];
    #pragma unroll
    for (int k = 0; k < 7; ++k)
        #pragma unroll
        for (int m = 0; m < 7; ++m) acc[k][m] = 0ull;

    // ---- stage 0: dims 0-63 (buffer 0); stage-1 fill still in flight
    cp_wait<1>();
    __syncwarp();          // all lanes of this warp have waited -> buffer 0 complete
    {
        const uint32_t base = mybuf;
        #pragma unroll 4
        for (int c = 0; c < 16; ++c) {
            ulonglong2 av[7];
            #pragma unroll
            for (int k = 0; k < 7; ++k) av[k] = lds128(base + aoff[k] + c * 16);
            #pragma unroll
            for (int m = 0; m < 7; ++m) {
                ulonglong2 bv = lds128(base + boff[m] + c * 16);
                #pragma unroll
                for (int k = 0; k < 7; ++k) {
                    acc[k][m] = fma2(av[k].x, bv.x, acc[k][m]);
                    acc[k][m] = fma2(av[k].y, bv.y, acc[k][m]);
                }
            }
        }
    }

    // ---- stage 1: dims 64-127 (buffer 1)
    cp_wait<0>();
    __syncwarp();
    {
        const uint32_t base = mybuf + BUFSZ;
        #pragma unroll 4
        for (int c = 0; c < 16; ++c) {
            ulonglong2 av[7];
            #pragma unroll
            for (int k = 0; k < 7; ++k) av[k] = lds128(base + aoff[k] + c * 16);
            #pragma unroll
            for (int m = 0; m < 7; ++m) {
                ulonglong2 bv = lds128(base + boff[m] + c * 16);
                #pragma unroll
                for (int k = 0; k < 7; ++k) {
                    acc[k][m] = fma2(av[k].x, bv.x, acc[k][m]);
                    acc[k][m] = fma2(av[k].y, bv.y, acc[k][m]);
                }
            }
        }
    }

    // ---- dense passthrough (direct from gmem; out rows only 4B-aligned)
    #pragma unroll
    for (int s = 0; s < 2; ++s) {
        float4 v = *reinterpret_cast<const float4*>(dense + (size_t)(b0 + s) * ND + lane * 4);
        float* od = out + (size_t)(b0 + s) * OUT_ROW;
        od[lane * 4 + 0] = v.x;
        od[lane * 4 + 1] = v.y;
        od[lane * 4 + 2] = v.z;
        od[lane * 4 + 3] = v.w;
    }

    // ---- epilogue: horizontal add, strict upper triangle of own sample
    // flat index (i,j), i<j: p = 26*i - i*(i-1)/2 + (j-i-1)
    float* orow = out + (size_t)(b0 + h) * OUT_ROW;
    #pragma unroll
    for (int k = 0; k < 7; ++k) {
        const int i = rg * 7 + k;
        #pragma unroll
        for (int m = 0; m < 7; ++m) {
            const int j = cg * 7 + m;
            if (i < 27 && j < 27 && j > i) {
                float lo = __uint_as_float((unsigned)(acc[k][m] & 0xffffffffull));
                float hi = __uint_as_float((unsigned)(acc[k][m] >> 32));
                int p = 26 * i - (i * (i - 1)) / 2 + (j - i - 1);
                orow[ND + p] = lo + hi;
            }
        }
    }
}

extern "C" void kernel_launch(void* const* d_in, const int* in_sizes, int n_in,
                              void* d_out, int out_size)
{
    const float* dense  = (const float*)d_in[0];
    const float* sparse = (const float*)d_in[1];
    float* out = (float*)d_out;

    cudaFuncSetAttribute(interaction_kernel,
                         cudaFuncAttributeMaxDynamicSharedMemorySize, CTASM);
    interaction_kernel<<<NB / (WPC * 2), WPC * 32, CTASM>>>(dense, sparse, out);
}

// round 12
// speedup vs baseline: 1.1357x; 1.1357x over previous
#include <cuda_runtime.h>
#include <cstdint>

#define NF 27
#define ND 128
#define NB 16384
#define OUT_ROW 479            // 128 + 27*26/2
#define WPC 4                  // warps per CTA; each warp = 2 samples
// quarter-row stage: feature f at f*144 (128B data + 16B pad); slot = 16*(f%8)
#define FOFF(f) ((f) * 144)
#define STGSZ 3904             // stage buffer (27*144=3888 -> 3904)
#define SMPSZ 7872             // per sample: 2 stage buffers + pad; == 64 (mod 128)
#define WARPSM (2 * SMPSZ)     // 15744
#define CTASM  (WPC * WARPSM)  // 62976 -> 3 CTAs/SM

__device__ __forceinline__ unsigned long long fma2(unsigned long long a,
                                                   unsigned long long b,
                                                   unsigned long long c) {
    unsigned long long d;
    asm("fma.rn.f32x2 %0, %1, %2, %3;" : "=l"(d) : "l"(a), "l"(b), "l"(c));
    return d;
}
__device__ __forceinline__ ulonglong2 lds128(uint32_t addr) {
    ulonglong2 v;
    asm volatile("ld.shared.v2.u64 {%0,%1}, [%2];" : "=l"(v.x), "=l"(v.y) : "r"(addr));
    return v;
}
__device__ __forceinline__ void cp16(uint32_t dst, const float* src) {
    asm volatile("cp.async.ca.shared.global [%0], [%1], 16;"
                 :: "r"(dst), "l"(__cvta_generic_to_global(src)) : "memory");
}
__device__ __forceinline__ void cp_commit() {
    asm volatile("cp.async.commit_group;" ::: "memory");
}
template <int N> __device__ __forceinline__ void cp_wait() {
    asm volatile("cp.async.wait_group %0;" :: "n"(N) : "memory");
}

// issue one stage fill (32 dims) for both samples of this warp into buffer bi
__device__ __forceinline__ void fill_stage(uint32_t sb, int lane, int b0,
                                           const float* dense, const float* sparse,
                                           int st, int bi) {
    const int q  = lane >> 4;          // sample
    const int fl = lane & 15;
    const uint32_t dst0 = sb + q * SMPSZ + bi * STGSZ;
    #pragma unroll
    for (int r = 0; r < 14; ++r) {
        const int flat = r * 16 + fl;  // feature*8 + chunk, < 216
        if (flat < 216) {
            const int f  = flat >> 3;
            const int ch = flat & 7;
            const float* src = (f == 0)
                ? dense  + (size_t)(b0 + q) * ND + st * 32 + ch * 4
                : sparse + ((size_t)(b0 + q) * 26 + (f - 1)) * ND + st * 32 + ch * 4;
            cp16(dst0 + f * 144 + ch * 16, src);
        }
    }
    cp_commit();
}

extern "C" __global__ void __launch_bounds__(WPC * 32, 3)
interaction_kernel(const float* __restrict__ dense,
                   const float* __restrict__ sparse,
                   float* __restrict__ out)
{
    extern __shared__ float smem[];
    uint32_t sb;
    asm("{ .reg .u64 t; cvta.to.shared.u64 t, %1; cvt.u32.u64 %0, t; }"
        : "=r"(sb) : "l"(smem));
    const int warp = threadIdx.x >> 5;
    const int lane = threadIdx.x & 31;
    sb += warp * WARPSM;

    const int b0 = (blockIdx.x * WPC + warp) * 2;   // warp's two samples

    // ---- prologue: prefill stages 0 and 1
    fill_stage(sb, lane, b0, dense, sparse, 0, 0);
    fill_stage(sb, lane, b0, dense, sparse, 1, 1);

    // ---- compute setup: half-warp h owns sample b0+h; 16-lane grid 4x4, 7x7 tile
    const int h  = lane >> 4;
    const int rg = (lane >> 2) & 3;
    const int cg = lane & 3;
    const uint32_t mybuf = sb + h * SMPSZ;

    uint32_t aoff[7], boff[7];
    #pragma unroll
    for (int k = 0; k < 7; ++k) {
        int r = rg * 7 + k; if (r > 26) r = 26;     // clamp; never stored
        aoff[k] = FOFF(r);
    }
    #pragma unroll
    for (int m = 0; m < 7; ++m) {
        int j = cg * 7 + m; if (j > 26) j = 26;
        boff[m] = FOFF(j);
    }

    unsigned long long acc[7][7];
    #pragma unroll
    for (int k = 0; k < 7; ++k)
        #pragma unroll
        for (int m = 0; m < 7; ++m) acc[k][m] = 0ull;

    // one stage of compute: 8 chunks x (7 a-loads, 7x(b-load + 14 FFMA2))
    #define COMPUTE_STAGE(BI)                                                   \
    {                                                                           \
        const uint32_t base = mybuf + (BI) * STGSZ;                             \
        _Pragma("unroll")                                                       \
        for (int c = 0; c < 8; ++c) {                                           \
            ulonglong2 av[7];                                                   \
            _Pragma("unroll")                                                   \
            for (int k = 0; k < 7; ++k) av[k] = lds128(base + aoff[k] + c * 16);\
            _Pragma("unroll")                                                   \
            for (int m = 0; m < 7; ++m) {                                       \
                ulonglong2 bv = lds128(base + boff[m] + c * 16);                \
                _Pragma("unroll")                                               \
                for (int k = 0; k < 7; ++k) {                                   \
                    acc[k][m] = fma2(av[k].x, bv.x, acc[k][m]);                 \
                    acc[k][m] = fma2(av[k].y, bv.y, acc[k][m]);                 \
                }                                                               \
            }                                                                   \
        }                                                                       \
    }

    // ---- pipelined mainloop over 4 stages
    cp_wait<1>(); __syncwarp();
    COMPUTE_STAGE(0)
    fill_stage(sb, lane, b0, dense, sparse, 2, 0);
    cp_wait<1>(); __syncwarp();
    COMPUTE_STAGE(1)
    fill_stage(sb, lane, b0, dense, sparse, 3, 1);
    cp_wait<1>(); __syncwarp();
    COMPUTE_STAGE(0)
    cp_wait<0>(); __syncwarp();
    COMPUTE_STAGE(1)

    // ---- dense passthrough (direct from gmem; out rows only 4B-aligned)
    #pragma unroll
    for (int s = 0; s < 2; ++s) {
        float4 v = *reinterpret_cast<const float4*>(dense + (size_t)(b0 + s) * ND + lane * 4);
        float* od = out + (size_t)(b0 + s) * OUT_ROW;
        od[lane * 4 + 0] = v.x;
        od[lane * 4 + 1] = v.y;
        od[lane * 4 + 2] = v.z;
        od[lane * 4 + 3] = v.w;
    }

    // ---- epilogue: horizontal add, strict upper triangle of own sample
    // flat index (i,j), i<j: p = 26*i - i*(i-1)/2 + (j-i-1)
    float* orow = out + (size_t)(b0 + h) * OUT_ROW;
    #pragma unroll
    for (int k = 0; k < 7; ++k) {
        const int i = rg * 7 + k;
        #pragma unroll
        for (int m = 0; m < 7; ++m) {
            const int j = cg * 7 + m;
            if (i < 27 && j < 27 && j > i) {
                float lo = __uint_as_float((unsigned)(acc[k][m] & 0xffffffffull));
                float hi = __uint_as_float((unsigned)(acc[k][m] >> 32));
                int p = 26 * i - (i * (i - 1)) / 2 + (j - i - 1);
                orow[ND + p] = lo + hi;
            }
        }
    }
}

extern "C" void kernel_launch(void* const* d_in, const int* in_sizes, int n_in,
                              void* d_out, int out_size)
{
    const float* dense  = (const float*)d_in[0];
    const float* sparse = (const float*)d_in[1];
    float* out = (float*)d_out;

    cudaFuncSetAttribute(interaction_kernel,
                         cudaFuncAttributeMaxDynamicSharedMemorySize, CTASM);
    interaction_kernel<<<NB / (WPC * 2), WPC * 32, CTASM>>>(dense, sparse, out);
}

// round 13
// speedup vs baseline: 2.0990x; 1.8481x over previous
#include <cuda_runtime.h>
#include <cuda_bf16.h>
#include <cstdint>

#define NF 27
#define ND 128
#define NB 16384
#define OUT_ROW 479            // 128 + 27*26/2
#define WPC 4                  // warps per CTA; 1 sample per warp
// per-warp smem: hi tile 32x128 bf16 (8KB, swizzled) then lo tile (8KB)
#define TILE_B 8192
#define WARPSM (2 * TILE_B)    // 16384
#define CTASM  (WPC * WARPSM)  // 65536 -> 3 CTAs/SM

// pack two f32 -> bf16x2 (elem order: lo first in memory)
__device__ __forceinline__ uint32_t pack_bf16x2(float lo, float hi) {
    uint32_t r;
    asm("cvt.rn.bf16x2.f32 %0, %1, %2;" : "=r"(r) : "f"(hi), "f"(lo));
    return r;
}
__device__ __forceinline__ void ldm_x4(uint32_t* r, uint32_t addr) {
    asm volatile("ldmatrix.sync.aligned.m8n8.x4.shared.b16 {%0,%1,%2,%3}, [%4];"
                 : "=r"(r[0]), "=r"(r[1]), "=r"(r[2]), "=r"(r[3]) : "r"(addr));
}
__device__ __forceinline__ void mma_bf16(float* d, const uint32_t* a,
                                         uint32_t b0, uint32_t b1) {
    asm volatile("mma.sync.aligned.m16n8k16.row.col.f32.bf16.bf16.f32 "
                 "{%0,%1,%2,%3}, {%4,%5,%6,%7}, {%8,%9}, {%0,%1,%2,%3};"
                 : "+f"(d[0]), "+f"(d[1]), "+f"(d[2]), "+f"(d[3])
                 : "r"(a[0]), "r"(a[1]), "r"(a[2]), "r"(a[3]), "r"(b0), "r"(b1));
}

extern "C" __global__ void __launch_bounds__(WPC * 32, 3)
interaction_kernel(const float* __restrict__ dense,
                   const float* __restrict__ sparse,
                   float* __restrict__ out)
{
    extern __shared__ char smem[];
    uint32_t sb;
    asm("{ .reg .u64 t; cvta.to.shared.u64 t, %1; cvt.u32.u64 %0, t; }"
        : "=r"(sb) : "l"(smem));
    const int warp = threadIdx.x >> 5;
    const int lane = threadIdx.x & 31;
    const uint32_t sHi = sb + warp * WARPSM;       // 32 rows x 256B, swizzled
    const uint32_t sLo = sHi + TILE_B;

    const int b = blockIdx.x * WPC + warp;         // sample
    float* orow = out + (size_t)b * OUT_ROW;

    // ---- fill: convert fp32 row -> bf16 hi/lo, swizzled STS.
    // element (row f, 16B-chunk c): byte = f*256 + ((c ^ (f&7))<<4)
    // lane covers dims 4*lane..+3 -> chunk c=lane>>1, half lane&1
    {
        const uint32_t hsel = (uint32_t)(lane & 1) << 3;
        #pragma unroll
        for (int bt = 0; bt < 3; ++bt) {
            float4 v[9];
            #pragma unroll
            for (int r = 0; r < 9; ++r) {
                const int f = bt * 9 + r;
                const float* src = (f == 0)
                    ? dense  + (size_t)b * ND
                    : sparse + ((size_t)b * 26 + (f - 1)) * ND;
                v[r] = *reinterpret_cast<const float4*>(src + lane * 4);
            }
            #pragma unroll
            for (int r = 0; r < 9; ++r) {
                const int f = bt * 9 + r;
                if (f == 0) {                       // dense passthrough (4B-aligned row)
                    orow[lane*4+0] = v[r].x; orow[lane*4+1] = v[r].y;
                    orow[lane*4+2] = v[r].z; orow[lane*4+3] = v[r].w;
                }
                uint32_t h0 = pack_bf16x2(v[r].x, v[r].y);
                uint32_t h1 = pack_bf16x2(v[r].z, v[r].w);
                float hx = __uint_as_float(h0 << 16);
                float hy = __uint_as_float(h0 & 0xffff0000u);
                float hz = __uint_as_float(h1 << 16);
                float hw = __uint_as_float(h1 & 0xffff0000u);
                uint32_t l0 = pack_bf16x2(v[r].x - hx, v[r].y - hy);
                uint32_t l1 = pack_bf16x2(v[r].z - hz, v[r].w - hw);
                const uint32_t off = (uint32_t)f * 256u
                    + ((uint32_t)(((lane >> 1) ^ (f & 7))) << 4) + hsel;
                asm volatile("st.shared.v2.b32 [%0], {%1,%2};"
                             :: "r"(sHi + off), "r"(h0), "r"(h1) : "memory");
                asm volatile("st.shared.v2.b32 [%0], {%1,%2};"
                             :: "r"(sLo + off), "r"(l0), "r"(l1) : "memory");
            }
        }
    }
    __syncwarp();

    // ---- ldmatrix base addresses (row part); chunk part varies per k-tile
    const int g4 = lane >> 3;                      // ldmatrix lane-group 0..3
    const int lr = lane & 7;
    // A x4 (M-tile mt): m0 rows0-7 c0 | m1 rows8-15 c0 | m2 rows0-7 c1 | m3 rows8-15 c1
    const uint32_t rowA = (uint32_t)(8 * (g4 & 1) + lr);
    const uint32_t cselA = (uint32_t)(g4 >> 1);
    // B x4 (pair q -> n-tiles 2q,2q+1): m0 n0-7 c0 | m1 n0-7 c1 | m2 n8-15 c0 | m3 n8-15 c1
    const uint32_t rowB = (uint32_t)(8 * (g4 >> 1) + lr);
    const uint32_t cselB = (uint32_t)(g4 & 1);

    uint32_t aBase[2], bBase[2];
    #pragma unroll
    for (int mt = 0; mt < 2; ++mt) aBase[mt] = sHi + (rowA + 16u * mt) * 256u;
    #pragma unroll
    for (int q = 0; q < 2; ++q)    bBase[q]  = sHi + (rowB + 16u * q) * 256u;

    float d[2][4][4];
    #pragma unroll
    for (int mt = 0; mt < 2; ++mt)
        #pragma unroll
        for (int nt = 0; nt < 4; ++nt)
            #pragma unroll
            for (int ri = 0; ri < 4; ++ri) d[mt][nt][ri] = 0.0f;

    // ---- mainloop: 8 k-tiles; D = Ah*Bh^T + Ah*Bl^T + Al*Bh^T
    #pragma unroll
    for (int kt = 0; kt < 8; ++kt) {
        uint32_t Ah[2][4], Al[2][4], Bh[2][4], Bl[2][4];
        const uint32_t ca = (((uint32_t)(2 * kt) + cselA) ^ (uint32_t)lr) << 4;
        const uint32_t cb = (((uint32_t)(2 * kt) + cselB) ^ (uint32_t)lr) << 4;
        #pragma unroll
        for (int mt = 0; mt < 2; ++mt) {
            ldm_x4(Ah[mt], aBase[mt] + ca);
            ldm_x4(Al[mt], aBase[mt] + TILE_B + ca);
        }
        #pragma unroll
        for (int q = 0; q < 2; ++q) {
            ldm_x4(Bh[q], bBase[q] + cb);
            ldm_x4(Bl[q], bBase[q] + TILE_B + cb);
        }
        #pragma unroll
        for (int mt = 0; mt < 2; ++mt)
            #pragma unroll
            for (int nt = 0; nt < 4; ++nt) {
                const int q = nt >> 1, s = (nt & 1) * 2;
                mma_bf16(d[mt][nt], Ah[mt], Bh[q][s], Bh[q][s + 1]);
                mma_bf16(d[mt][nt], Ah[mt], Bl[q][s], Bl[q][s + 1]);
                mma_bf16(d[mt][nt], Al[mt], Bh[q][s], Bh[q][s + 1]);
            }
    }

    // ---- epilogue: D fragment (i,j) -> strict upper triangle scatter
    // lane l: i = 16mt + l/4 + 8*(ri>>1), j = 8nt + 2*(l%4) + (ri&1)
    const int g = lane >> 2, tig = lane & 3;
    #pragma unroll
    for (int mt = 0; mt < 2; ++mt)
        #pragma unroll
        for (int nt = 0; nt < 4; ++nt)
            #pragma unroll
            for (int ri = 0; ri < 4; ++ri) {
                const int i = 16 * mt + g + 8 * (ri >> 1);
                const int j = 8 * nt + 2 * tig + (ri & 1);
                if (i < NF && j < NF && j > i) {
                    const int p = 26 * i - ((i * (i - 1)) >> 1) + (j - i - 1);
                    orow[ND + p] = d[mt][nt][ri];
                }
            }
}

extern "C" void kernel_launch(void* const* d_in, const int* in_sizes, int n_in,
                              void* d_out, int out_size)
{
    const float* dense  = (const float*)d_in[0];
    const float* sparse = (const float*)d_in[1];
    float* out = (float*)d_out;

    cudaFuncSetAttribute(interaction_kernel,
                         cudaFuncAttributeMaxDynamicSharedMemorySize, CTASM);
    interaction_kernel<<<NB / WPC, WPC * 32, CTASM>>>(dense, sparse, out);
}

// round 15
// speedup vs baseline: 2.1857x; 1.0413x over previous
#include <cuda_runtime.h>
#include <cuda_bf16.h>
#include <cstdint>

#define NF 27
#define ND 128
#define NB 16384
#define OUT_ROW 479            // 128 + 27*26/2
#define WPC 4                  // warps per CTA; 1 sample per warp
// per-warp smem: hi tile 32x128 bf16 (8KB, swizzled) then lo tile (8KB)
#define TILE_B 8192
#define WARPSM (2 * TILE_B)    // 16384
#define CTASM  (WPC * WARPSM)  // 65536 -> 3 CTAs/SM

// pack two f32 -> bf16x2 (elem order: lo first in memory)
__device__ __forceinline__ uint32_t pack_bf16x2(float lo, float hi) {
    uint32_t r;
    asm("cvt.rn.bf16x2.f32 %0, %1, %2;" : "=r"(r) : "f"(hi), "f"(lo));
    return r;
}
__device__ __forceinline__ void ldm_x4(uint32_t* r, uint32_t addr) {
    asm volatile("ldmatrix.sync.aligned.m8n8.x4.shared.b16 {%0,%1,%2,%3}, [%4];"
                 : "=r"(r[0]), "=r"(r[1]), "=r"(r[2]), "=r"(r[3]) : "r"(addr));
}
__device__ __forceinline__ void mma_bf16(float* d, const uint32_t* a,
                                         uint32_t b0, uint32_t b1) {
    asm volatile("mma.sync.aligned.m16n8k16.row.col.f32.bf16.bf16.f32 "
                 "{%0,%1,%2,%3}, {%4,%5,%6,%7}, {%8,%9}, {%0,%1,%2,%3};"
                 : "+f"(d[0]), "+f"(d[1]), "+f"(d[2]), "+f"(d[3])
                 : "r"(a[0]), "r"(a[1]), "r"(a[2]), "r"(a[3]), "r"(b0), "r"(b1));
}

extern "C" __global__ void __launch_bounds__(WPC * 32, 3)
interaction_kernel(const float* __restrict__ dense,
                   const float* __restrict__ sparse,
                   float* __restrict__ out)
{
    extern __shared__ char smem[];
    uint32_t sb;
    asm("{ .reg .u64 t; cvta.to.shared.u64 t, %1; cvt.u32.u64 %0, t; }"
        : "=r"(sb) : "l"(smem));
    const int warp = threadIdx.x >> 5;
    const int lane = threadIdx.x & 31;
    const uint32_t sHi = sb + warp * WARPSM;       // 32 rows x 256B, swizzled
    const uint32_t sLo = sHi + TILE_B;

    const int b = blockIdx.x * WPC + warp;         // sample
    float* orow = out + (size_t)b * OUT_ROW;

    // ---- fill: convert fp32 row -> bf16 hi/lo, swizzled STS.
    // element (row f, 16B-chunk c): byte = f*256 + ((c ^ (f&7))<<4)
    // lane covers dims 4*lane..+3 -> chunk c=lane>>1, half lane&1
    {
        const uint32_t hsel = (uint32_t)(lane & 1) << 3;
        #pragma unroll
        for (int bt = 0; bt < 3; ++bt) {
            float4 v[9];
            #pragma unroll
            for (int r = 0; r < 9; ++r) {
                const int f = bt * 9 + r;
                const float* src = (f == 0)
                    ? dense  + (size_t)b * ND
                    : sparse + ((size_t)b * 26 + (f - 1)) * ND;
                v[r] = *reinterpret_cast<const float4*>(src + lane * 4);
            }
            #pragma unroll
            for (int r = 0; r < 9; ++r) {
                const int f = bt * 9 + r;
                if (f == 0) {                       // dense passthrough (4B-aligned row)
                    orow[lane*4+0] = v[r].x; orow[lane*4+1] = v[r].y;
                    orow[lane*4+2] = v[r].z; orow[lane*4+3] = v[r].w;
                }
                uint32_t h0 = pack_bf16x2(v[r].x, v[r].y);
                uint32_t h1 = pack_bf16x2(v[r].z, v[r].w);
                float hx = __uint_as_float(h0 << 16);
                float hy = __uint_as_float(h0 & 0xffff0000u);
                float hz = __uint_as_float(h1 << 16);
                float hw = __uint_as_float(h1 & 0xffff0000u);
                uint32_t l0 = pack_bf16x2(v[r].x - hx, v[r].y - hy);
                uint32_t l1 = pack_bf16x2(v[r].z - hz, v[r].w - hw);
                const uint32_t off = (uint32_t)f * 256u
                    + ((uint32_t)(((lane >> 1) ^ (f & 7))) << 4) + hsel;
                asm volatile("st.shared.v2.b32 [%0], {%1,%2};"
                             :: "r"(sHi + off), "r"(h0), "r"(h1) : "memory");
                asm volatile("st.shared.v2.b32 [%0], {%1,%2};"
                             :: "r"(sLo + off), "r"(l0), "r"(l1) : "memory");
            }
        }
    }
    __syncwarp();

    // ---- ldmatrix addressing (A-fragments only; B-frags are register aliases)
    const int g4 = lane >> 3;                      // ldmatrix lane-group 0..3
    const int lr = lane & 7;
    // A x4 (M-tile mt): m0 rows0-7 c0 | m1 rows8-15 c0 | m2 rows0-7 c1 | m3 rows8-15 c1
    const uint32_t rowA = (uint32_t)(8 * (g4 & 1) + lr);
    const uint32_t cselA = (uint32_t)(g4 >> 1);
    uint32_t aBase[2];
    #pragma unroll
    for (int mt = 0; mt < 2; ++mt) aBase[mt] = sHi + (rowA + 16u * mt) * 256u;

    // 6 needed D tiles: t=0..3 -> (mt0,nt t); t=4,5 -> (mt1, nt t-2)
    float d[6][4];
    #pragma unroll
    for (int t = 0; t < 6; ++t)
        #pragma unroll
        for (int ri = 0; ri < 4; ++ri) d[t][ri] = 0.0f;

    // ---- mainloop: 8 k-tiles; D = Ah*Bh^T + Ah*Bl^T + Al*Bh^T
    // B-frag aliasing (Gram symmetry): for n-tile nt, b0 = A[nt>>1][nt&1],
    // b1 = A[nt>>1][2+(nt&1)]  (same lane layout as A-frag regs)
    #pragma unroll
    for (int kt = 0; kt < 8; ++kt) {
        uint32_t Ah[2][4], Al[2][4];
        const uint32_t ca = (((uint32_t)(2 * kt) + cselA) ^ (uint32_t)lr) << 4;
        #pragma unroll
        for (int mt = 0; mt < 2; ++mt) {
            ldm_x4(Ah[mt], aBase[mt] + ca);
            ldm_x4(Al[mt], aBase[mt] + TILE_B + ca);
        }
        #pragma unroll
        for (int t = 0; t < 6; ++t) {
            const int mt = (t < 4) ? 0 : 1;
            const int nt = (t < 4) ? t : (t - 2);
            const int bq = nt >> 1, bh = nt & 1;
            const uint32_t bh0 = Ah[bq][bh], bh1 = Ah[bq][2 + bh];
            const uint32_t bl0 = Al[bq][bh], bl1 = Al[bq][2 + bh];
            mma_bf16(d[t], Ah[mt], bh0, bh1);
            mma_bf16(d[t], Ah[mt], bl0, bl1);
            mma_bf16(d[t], Al[mt], bh0, bh1);
        }
    }

    // ---- epilogue: D fragment (i,j) -> strict upper triangle scatter
    // lane l: i = 16mt + l/4 + 8*(ri>>1), j = 8nt + 2*(l%4) + (ri&1)
    const int g = lane >> 2, tig = lane & 3;
    #pragma unroll
    for (int t = 0; t < 6; ++t) {
        const int mt = (t < 4) ? 0 : 1;
        const int nt = (t < 4) ? t : (t - 2);
        #pragma unroll
        for (int ri = 0; ri < 4; ++ri) {
            const int i = 16 * mt + g + 8 * (ri >> 1);
            const int j = 8 * nt + 2 * tig + (ri & 1);
            if (i < NF && j < NF && j > i) {
                const int p = 26 * i - ((i * (i - 1)) >> 1) + (j - i - 1);
                orow[ND + p] = d[t][ri];
            }
        }
    }
}

extern "C" void kernel_launch(void* const* d_in, const int* in_sizes, int n_in,
                              void* d_out, int out_size)
{
    const float* dense  = (const float*)d_in[0];
    const float* sparse = (const float*)d_in[1];
    float* out = (float*)d_out;

    cudaFuncSetAttribute(interaction_kernel,
                         cudaFuncAttributeMaxDynamicSharedMemorySize, CTASM);
    interaction_kernel<<<NB / WPC, WPC * 32, CTASM>>>(dense, sparse, out);
}